// round 16
// baseline (speedup 1.0000x reference)
#include <cuda_runtime.h>
#include <math.h>

#define NPIX  (512*1024)
#define NB    8
#define KBINS 16
#define CBINS 4
#define NACC  (KBINS*CBINS + CBINS)   // 64 p_cl + 4 p_l = 68
#define TPB   128
#define GRID  592                     // 148 SMs * 4 blocks, one wave

__device__ float g_acc[NACC];         // zero at module load; reset by last block each run
__device__ unsigned int g_ticket;     // zero at module load; reset by last block each run

__device__ __forceinline__ float tanh_fast(float x) {
    float r;
    asm("tanh.approx.f32 %0, %1;" : "=f"(r) : "f"(x));
    return r;
}

__global__ void __launch_bounds__(TPB, 4)
nid_kernel(const float* __restrict__ cam, const float* __restrict__ lab,
           float* __restrict__ out)
{
    // Two independent per-thread 16-bin histogram rows (even/odd batches) in
    // SEPARATE arrays: two distinct base pointers -> two independent RMW
    // chains the compiler can interleave. Stride 17 keeps 17*tid mod 32
    // bank-bijective per row.
    __shared__ float pcs0[TPB * 17];
    __shared__ float pcs1[TPB * 17];
    float* __restrict__ myPc0 = &pcs0[threadIdx.x * 17];
    float* __restrict__ myPc1 = &pcs1[threadIdx.x * 17];

    float acc_cl[KBINS * CBINS];
    float acc_l[CBINS];
#pragma unroll
    for (int i = 0; i < KBINS * CBINS; i++) acc_cl[i] = 0.0f;
#pragma unroll
    for (int c = 0; c < CBINS; c++) acc_l[c] = 0.0f;

    const int stride = GRID * TPB;
#pragma unroll 1
    for (int n = blockIdx.x * TPB + threadIdx.x; n < NPIX; n += stride) {
        float PlS[CBINS];
#pragma unroll
        for (int c = 0; c < CBINS; c++) PlS[c] = 0.0f;
#pragma unroll
        for (int k = 0; k < KBINS; k++) { myPc0[k] = 0.0f; myPc1[k] = 0.0f; }

#pragma unroll
        for (int p = 0; p < NB / 2; p++) {
            // ======== even batch (chain 0) + odd batch (chain 1) ========
#pragma unroll
            for (int s = 0; s < 2; s++) {
                const int b = 2 * p + s;
                float* __restrict__ myPc = s ? myPc1 : myPc0;

                // ---- camera: g16 = 16*gray; only edges ie-1..ie+2 live.
                // w_j = tanh(6.25*(fr+1-j)); masses (x0.5 cancels later):
                // bin ie-2: 1-w0, ie-1: w0-w1, ie: w1-w2, ie+1: w2-w3.
                const float* cb = cam + (size_t)b * 3 * NPIX + n;
                float g16 = (cb[0] + cb[NPIX] + cb[2 * NPIX]) * (16.0f / 3.0f);
                float ef  = floorf(g16);
                float fr  = g16 - ef;
                int   ie  = (int)ef;
                float w0 = tanh_fast(fmaf(6.25f, fr,   6.25f));
                float w1 = tanh_fast(6.25f * fr);
                float w2 = tanh_fast(fmaf(6.25f, fr,  -6.25f));
                float w3 = tanh_fast(fmaf(6.25f, fr, -12.5f));
                float m0 = 1.0f - w0;
                float m1 = w0 - w1;
                float m2 = w1 - w2;
                float m3 = w2 - w3;
                int base = ie - 2;
                if ((unsigned)(base + 0) < 16u) myPc[base + 0] += m0;
                if ((unsigned)(base + 1) < 16u) myPc[base + 1] += m1;
                if ((unsigned)(base + 2) < 16u) myPc[base + 2] += m2;
                if ((unsigned)(base + 3) < 16u) myPc[base + 3] += m3;

                // ---- label soft-argmax (beta = 500), exact R4 path ----
                const float* lbp = lab + (size_t)b * 4 * NPIX + n;
                float l0 = lbp[0];
                float l1 = lbp[NPIX];
                float l2 = lbp[2 * NPIX];
                float l3 = lbp[3 * NPIX];
                float m  = fmaxf(fmaxf(l0, l1), fmaxf(l2, l3));
                float e0 = __expf((l0 - m) * 500.0f);
                float e1 = __expf((l1 - m) * 500.0f);
                float e2 = __expf((l2 - m) * 500.0f);
                float e3 = __expf((l3 - m) * 500.0f);
                float es = e0 + e1 + e2 + e3;   // >= 1, +1e-12 is an fp32 no-op
                float labv = __fdividef(fmaf(3.0f, e3, fmaf(2.0f, e2, e1)), es);

                // single non-saturated label-edge sigmoid
                float u  = labv + 0.5f;
                float ce = rintf(u);
                float x  = (u - ce) * 500.0f;               // tanh half-arg
                float sg = fmaf(0.5f, tanh_fast(x), 0.5f);
                int   ic = (int)ce;
#pragma unroll
                for (int c = 0; c < CBINS; c++) {
                    float addv = (ic == c) ? sg : ((ic == c + 1) ? (1.0f - sg) : 0.0f);
                    PlS[c] += addv;
                }
            }
        }

        // readback (merge chains) + outer product: acc_cl[k][c] += Pc[k]*PlS[c]
#pragma unroll
        for (int k = 0; k < KBINS; k++) {
            float pck = myPc0[k] + myPc1[k];
#pragma unroll
            for (int c = 0; c < CBINS; c++)
                acc_cl[k * CBINS + c] = fmaf(pck, PlS[c], acc_cl[k * CBINS + c]);
        }
#pragma unroll
        for (int c = 0; c < CBINS; c++) acc_l[c] += PlS[c];
    }

    // ---- block reduction: warp shuffle -> shared -> global atomics ----
    __syncthreads();   // done with pcs*; barrier before red[] reuse region
    __shared__ float red[TPB / 32][NACC];
    unsigned lane = threadIdx.x & 31u;
    unsigned wrp  = threadIdx.x >> 5;

#pragma unroll
    for (int i = 0; i < KBINS * CBINS; i++) {
        float v = acc_cl[i];
        v += __shfl_down_sync(0xffffffffu, v, 16);
        v += __shfl_down_sync(0xffffffffu, v, 8);
        v += __shfl_down_sync(0xffffffffu, v, 4);
        v += __shfl_down_sync(0xffffffffu, v, 2);
        v += __shfl_down_sync(0xffffffffu, v, 1);
        if (lane == 0) red[wrp][i] = v;
    }
#pragma unroll
    for (int c = 0; c < CBINS; c++) {
        float v = acc_l[c];
        v += __shfl_down_sync(0xffffffffu, v, 16);
        v += __shfl_down_sync(0xffffffffu, v, 8);
        v += __shfl_down_sync(0xffffffffu, v, 4);
        v += __shfl_down_sync(0xffffffffu, v, 2);
        v += __shfl_down_sync(0xffffffffu, v, 1);
        if (lane == 0) red[wrp][KBINS * CBINS + c] = v;
    }
    __syncthreads();
    if (threadIdx.x < NACC) {
        float s = red[0][threadIdx.x] + red[1][threadIdx.x]
                + red[2][threadIdx.x] + red[3][threadIdx.x];
        atomicAdd(&g_acc[threadIdx.x], s);
    }
    __threadfence();   // publish g_acc contributions before taking a ticket
    __syncthreads();

    // ---- last-block finalize ----
    __shared__ unsigned int s_ticket;
    if (threadIdx.x == 0) s_ticket = atomicAdd(&g_ticket, 1u);
    __syncthreads();
    if (s_ticket != (unsigned)(GRID - 1)) return;

    if (threadIdx.x == 0) {
        __threadfence();  // acquire: see all blocks' atomics

        float pcl[KBINS * CBINS];
        float pl[CBINS];
        float scl = 0.0f, sl = 0.0f;
#pragma unroll
        for (int i = 0; i < KBINS * CBINS; i++) { pcl[i] = g_acc[i]; scl += pcl[i]; }
#pragma unroll
        for (int c = 0; c < CBINS; c++) { pl[c] = g_acc[KBINS * CBINS + c]; sl += pl[c]; }

        float inv_scl = 1.0f / scl;
        float inv_sl  = 1.0f / sl;

        float pc[KBINS];
#pragma unroll
        for (int k = 0; k < KBINS; k++) {
            float s = pcl[k * 4 + 0] + pcl[k * 4 + 1] + pcl[k * 4 + 2] + pcl[k * 4 + 3];
            pc[k] = s * inv_scl;   // row-marginal == normalized p_c
        }
#pragma unroll
        for (int c = 0; c < CBINS; c++) pl[c] *= inv_sl;

        float I = 0.0f, H = 0.0f;
#pragma unroll
        for (int k = 0; k < KBINS; k++) {
#pragma unroll
            for (int c = 0; c < CBINS; c++) {
                float p  = pcl[k * CBINS + c] * inv_scl;
                float lp = logf(p + 1e-7f);
                float lo = logf(pc[k] * pl[c] + 1e-7f);
                H -= p * lp;
                I += p * (lp - lo);
            }
        }
        float nid = 1.0f - I / H;
        out[0] = (nid - 0.95f) * 20.0f;

        // reset for next graph replay (deterministic across launches)
#pragma unroll
        for (int i = 0; i < NACC; i++) g_acc[i] = 0.0f;
        __threadfence();
        atomicExch(&g_ticket, 0u);
    }
}

extern "C" void kernel_launch(void* const* d_in, const int* in_sizes, int n_in,
                              void* d_out, int out_size)
{
    const float* cam = (const float*)d_in[0];   // (8,3,512,1024) fp32
    const float* lab = (const float*)d_in[1];   // (8,4,512,1024) fp32
    float* out = (float*)d_out;

    nid_kernel<<<GRID, TPB>>>(cam, lab, out);
}

// round 17
// speedup vs baseline: 1.0642x; 1.0642x over previous
#include <cuda_runtime.h>
#include <math.h>

#define NPIX  (512*1024)
#define NB    8
#define KBINS 16
#define CBINS 4
#define NACC  (KBINS*CBINS + CBINS)   // 64 p_cl + 4 p_l = 68
#define TPB   128
#define GRID  592                     // 148 SMs * 4 blocks, one wave
#define RW    29                      // smem row stride (odd -> bank-bijective)
// row layout per thread: [0..18] camera bins k at idx k+2 (margins 0,1,18)
//                        [21..26] label bins c at idx c+22 (margins 21,26)

__device__ float g_acc[NACC];         // zero at module load; reset by last block each run
__device__ unsigned int g_ticket;     // zero at module load; reset by last block each run

__device__ __forceinline__ float tanh_fast(float x) {
    float r;
    asm("tanh.approx.f32 %0, %1;" : "=f"(r) : "f"(x));
    return r;
}

__global__ void __launch_bounds__(TPB, 4)
nid_kernel(const float* __restrict__ cam, const float* __restrict__ lab,
           float* __restrict__ out)
{
    __shared__ float hist[TPB * RW];
    float* __restrict__ my = &hist[threadIdx.x * RW];

    float acc_cl[KBINS * CBINS];
    float acc_l[CBINS];
#pragma unroll
    for (int i = 0; i < KBINS * CBINS; i++) acc_cl[i] = 0.0f;
#pragma unroll
    for (int c = 0; c < CBINS; c++) acc_l[c] = 0.0f;

    const int stride = GRID * TPB;
#pragma unroll 1
    for (int n = blockIdx.x * TPB + threadIdx.x; n < NPIX; n += stride) {
#pragma unroll
        for (int k = 0; k < 27; k++) my[k] = 0.0f;

#pragma unroll
        for (int b = 0; b < NB; b++) {
            // ---- camera: g16 = 16*gray; only edges ie-1..ie+2 live.
            // w_j = tanh(6.25*(fr+1-j)); tanh-scale masses (x0.5 cancels in
            // the normalization): bin ie-2+j gets {1-w0, w0-w1, w1-w2, w2-w3}.
            // Stored at idx (bin+2) = ie+j; margins absorb out-of-range bins.
            const float* cb = cam + (size_t)b * 3 * NPIX + n;
            float g16 = (cb[0] + cb[NPIX] + cb[2 * NPIX]) * (16.0f / 3.0f);
            float ef  = floorf(g16);
            float fr  = g16 - ef;
            int   ie  = (int)ef;
            float w0 = tanh_fast(fmaf(6.25f, fr,   6.25f));
            float w1 = tanh_fast(6.25f * fr);
            float w2 = tanh_fast(fmaf(6.25f, fr,  -6.25f));
            float w3 = tanh_fast(fmaf(6.25f, fr, -12.5f));
            my[ie + 0] += 1.0f - w0;
            my[ie + 1] += w0 - w1;
            my[ie + 2] += w1 - w2;
            my[ie + 3] += w2 - w3;

            // ---- label soft-argmax (beta = 500), exact R4 math ----
            const float* lbp = lab + (size_t)b * 4 * NPIX + n;
            float l0 = lbp[0];
            float l1 = lbp[NPIX];
            float l2 = lbp[2 * NPIX];
            float l3 = lbp[3 * NPIX];
            float m  = fmaxf(fmaxf(l0, l1), fmaxf(l2, l3));
            float e0 = __expf((l0 - m) * 500.0f);
            float e1 = __expf((l1 - m) * 500.0f);
            float e2 = __expf((l2 - m) * 500.0f);
            float e3 = __expf((l3 - m) * 500.0f);
            float es = e0 + e1 + e2 + e3;   // >= 1, +1e-12 is an fp32 no-op
            float labv = __fdividef(fmaf(3.0f, e3, fmaf(2.0f, e2, e1)), es);

            // single non-saturated label-edge sigmoid; 2 scatter RMWs replace
            // the 4-way select chain. bin ic gets sg (idx 22+ic), bin ic-1
            // gets 1-sg (idx 21+ic); margins 21/26 absorb ic=0/ic=4 spill.
            float u  = labv + 0.5f;
            float ce = rintf(u);
            float x  = (u - ce) * 500.0f;               // tanh half-arg
            float sg = fmaf(0.5f, tanh_fast(x), 0.5f);
            int   ic = (int)ce;
            my[22 + ic] += sg;
            my[21 + ic] += 1.0f - sg;
        }

        // readback + outer product: acc_cl[k][c] += Pc[k] * PlS[c]
        float PlS[CBINS];
#pragma unroll
        for (int c = 0; c < CBINS; c++) {
            PlS[c] = my[22 + c];
            acc_l[c] += PlS[c];
        }
#pragma unroll
        for (int k = 0; k < KBINS; k++) {
            float pck = my[k + 2];
#pragma unroll
            for (int c = 0; c < CBINS; c++)
                acc_cl[k * CBINS + c] = fmaf(pck, PlS[c], acc_cl[k * CBINS + c]);
        }
    }

    // ---- block reduction: warp shuffle -> shared -> global atomics ----
    __syncthreads();   // done with hist; barrier before red[] region reuse
    __shared__ float red[TPB / 32][NACC];
    unsigned lane = threadIdx.x & 31u;
    unsigned wrp  = threadIdx.x >> 5;

#pragma unroll
    for (int i = 0; i < KBINS * CBINS; i++) {
        float v = acc_cl[i];
        v += __shfl_down_sync(0xffffffffu, v, 16);
        v += __shfl_down_sync(0xffffffffu, v, 8);
        v += __shfl_down_sync(0xffffffffu, v, 4);
        v += __shfl_down_sync(0xffffffffu, v, 2);
        v += __shfl_down_sync(0xffffffffu, v, 1);
        if (lane == 0) red[wrp][i] = v;
    }
#pragma unroll
    for (int c = 0; c < CBINS; c++) {
        float v = acc_l[c];
        v += __shfl_down_sync(0xffffffffu, v, 16);
        v += __shfl_down_sync(0xffffffffu, v, 8);
        v += __shfl_down_sync(0xffffffffu, v, 4);
        v += __shfl_down_sync(0xffffffffu, v, 2);
        v += __shfl_down_sync(0xffffffffu, v, 1);
        if (lane == 0) red[wrp][KBINS * CBINS + c] = v;
    }
    __syncthreads();
    if (threadIdx.x < NACC) {
        float s = red[0][threadIdx.x] + red[1][threadIdx.x]
                + red[2][threadIdx.x] + red[3][threadIdx.x];
        atomicAdd(&g_acc[threadIdx.x], s);
    }
    __threadfence();   // publish g_acc contributions before taking a ticket
    __syncthreads();

    // ---- last-block finalize ----
    __shared__ unsigned int s_ticket;
    if (threadIdx.x == 0) s_ticket = atomicAdd(&g_ticket, 1u);
    __syncthreads();
    if (s_ticket != (unsigned)(GRID - 1)) return;

    if (threadIdx.x == 0) {
        __threadfence();  // acquire: see all blocks' atomics

        float pcl[KBINS * CBINS];
        float pl[CBINS];
        float scl = 0.0f, sl = 0.0f;
#pragma unroll
        for (int i = 0; i < KBINS * CBINS; i++) { pcl[i] = g_acc[i]; scl += pcl[i]; }
#pragma unroll
        for (int c = 0; c < CBINS; c++) { pl[c] = g_acc[KBINS * CBINS + c]; sl += pl[c]; }

        float inv_scl = 1.0f / scl;
        float inv_sl  = 1.0f / sl;

        float pc[KBINS];
#pragma unroll
        for (int k = 0; k < KBINS; k++) {
            float s = pcl[k * 4 + 0] + pcl[k * 4 + 1] + pcl[k * 4 + 2] + pcl[k * 4 + 3];
            pc[k] = s * inv_scl;   // row-marginal == normalized p_c
        }
#pragma unroll
        for (int c = 0; c < CBINS; c++) pl[c] *= inv_sl;

        float I = 0.0f, H = 0.0f;
#pragma unroll
        for (int k = 0; k < KBINS; k++) {
#pragma unroll
            for (int c = 0; c < CBINS; c++) {
                float p  = pcl[k * CBINS + c] * inv_scl;
                float lp = logf(p + 1e-7f);
                float lo = logf(pc[k] * pl[c] + 1e-7f);
                H -= p * lp;
                I += p * (lp - lo);
            }
        }
        float nid = 1.0f - I / H;
        out[0] = (nid - 0.95f) * 20.0f;

        // reset for next graph replay (deterministic across launches)
#pragma unroll
        for (int i = 0; i < NACC; i++) g_acc[i] = 0.0f;
        __threadfence();
        atomicExch(&g_ticket, 0u);
    }
}

extern "C" void kernel_launch(void* const* d_in, const int* in_sizes, int n_in,
                              void* d_out, int out_size)
{
    const float* cam = (const float*)d_in[0];   // (8,3,512,1024) fp32
    const float* lab = (const float*)d_in[1];   // (8,4,512,1024) fp32
    float* out = (float*)d_out;

    nid_kernel<<<GRID, TPB>>>(cam, lab, out);
}